// round 14
// baseline (speedup 1.0000x reference)
#include <cuda_runtime.h>
#include <cuda_fp16.h>
#include <cuda_bf16.h>
#include <cstdint>

#define BB 128
#define LL 100
#define DD 512
#define EE 8
#define K0 900
#define KP 912          // 19 * 48
#define KC 48
#define NCH 19
#define MT 112          // padded M (7 x m16)
#define OUTM (BB*LL*DD)

// scratch (device globals; no allocation allowed)
__device__ __half g_wh[(size_t)BB*DD*KP];   // mixed weights hi, [b][n][k], 119.5MB
__device__ __half g_wl[(size_t)BB*DD*KP];   // mixed weights lo

__device__ __forceinline__ uint32_t su32(const void* p){
  uint32_t a;
  asm("{ .reg .u64 t; cvta.to.shared.u64 t, %1; cvt.u32.u64 %0, t; }":"=r"(a):"l"(p));
  return a;
}
// swizzled byte offset inside a [rows][64 halves] tile (128B rows, SW over 16B groups)
__device__ __forceinline__ int boff(int r,int c){
  return r*128 + ((((c>>3)^(r&7))<<4) | ((c&7)<<1));
}
#define LDM4(r0,r1,r2,r3,a) \
  asm volatile("ldmatrix.sync.aligned.m8n8.x4.shared.b16 {%0,%1,%2,%3},[%4];" \
    :"=r"(r0),"=r"(r1),"=r"(r2),"=r"(r3):"r"(a))
#define MMA(c,a,b0,b1) \
  asm volatile("mma.sync.aligned.m16n8k16.row.col.f32.f16.f16.f32 " \
    "{%0,%1,%2,%3},{%4,%5,%6,%7},{%8,%9},{%0,%1,%2,%3};" \
    :"+f"((c)[0]),"+f"((c)[1]),"+f"((c)[2]),"+f"((c)[3]) \
    :"r"((a)[0]),"r"((a)[1]),"r"((a)[2]),"r"((a)[3]),"r"(b0),"r"(b1))

__device__ __forceinline__ void cpa16(uint32_t dst, const __half* src){
  unsigned long long g = __cvta_generic_to_global((const void*)src);
  asm volatile("cp.async.cg.shared.global [%0], [%1], 16;" :: "r"(dst), "l"(g));
}
#define CP_COMMIT() asm volatile("cp.async.commit_group;":::"memory")
#define CP_WAIT1()  asm volatile("cp.async.wait_group 1;":::"memory")
#define CP_WAIT0()  asm volatile("cp.async.wait_group 0;":::"memory")

__device__ __forceinline__ float bf16r(float x){
  return __bfloat162float(__float2bfloat16_rn(x));
}

// returns true if c0 is the int mask (row 0 bit-patterns all <= 1)
__device__ __forceinline__ bool c0_is_mask(const float* c0){
  const unsigned* u0 = (const unsigned*)c0;
  bool m = true;
#pragma unroll
  for(int e=0;e<EE;e++) if(u0[e] > 1u) m = false;
  return m;
}
// compute renormalized gates for batch row b into g[8]; returns pre-renorm sum
__device__ __forceinline__ float gates_row(const float* logits, const int* masks,
                                           int b, float* g){
  float v[EE]; float mx = -1e30f;
#pragma unroll
  for(int e=0;e<EE;e++){ v[e]=logits[b*EE+e]; mx=fmaxf(mx,v[e]); }
  float s=0.f;
#pragma unroll
  for(int e=0;e<EE;e++){ v[e]=expf(v[e]-mx); s+=v[e]; }
  float inv=1.f/s, gs=0.f;
#pragma unroll
  for(int e=0;e<EE;e++){ float r=v[e]*inv*((masks[b*EE+e]==1)?1.f:0.f); v[e]=r; gs+=r; }
  float rn=1.f/(gs+1e-9f);
#pragma unroll
  for(int e=0;e<EE;e++) g[e]=v[e]*rn;
  return gs;
}

// ------------- kernel 1: Wmix[b][n][k] = sum_e g[b,e] W[e,k,n], fp16 hi/lo ---
// grid (4 k-chunks of 256, 64 n-chunks of 8), 256 threads. Gates computed
// inline; block (0,0) also writes the guide-loss tail.
__global__ __launch_bounds__(256) void k_mix(const float* __restrict__ W,
        const float* __restrict__ c0, const float* __restrict__ c1,
        float* __restrict__ out, int tail){
  __shared__ float wt[EE][8][264];
  __shared__ float gsh[BB*EE];
  __shared__ float red[BB];
  int tid = threadIdx.x;
  int kb = blockIdx.x*256, nb = blockIdx.y*8;
  bool m0 = c0_is_mask(c0);
  const float* logits = m0 ? c1 : c0;
  const int*   masks  = m0 ? (const int*)c0 : (const int*)c1;
  if(tid < BB){
    float g[EE];
    red[tid] = gates_row(logits, masks, tid, g);
#pragma unroll
    for(int e=0;e<EE;e++) gsh[tid*EE+e] = g[e];
  }
  for(int i=tid;i<EE*256*8;i+=256){
    int e=i>>11, k2=(i>>3)&255, n2=i&7;
    int k=kb+k2;
    wt[e][n2][k2] = (k<K0) ? W[((size_t)e*K0+k)*DD + nb+n2] : 0.f;
  }
  __syncthreads();
  if(blockIdx.x==0 && blockIdx.y==0 && tid==0){
    float t=0.f;
    for(int i=0;i<BB;i++) t+=red[i];
    float loss = 1.f - t/128.f; loss*=loss;
    for(int i=0;i<tail;i++) out[OUTM+i]=loss;
  }
  int w = tid>>5, l = tid&31;
  int ko = l*8;
  bool act = (kb + ko) < KP;         // kb=768 chunk: lanes 0..17 only
  float wr[EE][8];
#pragma unroll
  for(int e=0;e<EE;e++){
    *(float4*)&wr[e][0] = *(float4*)&wt[e][w][ko];
    *(float4*)&wr[e][4] = *(float4*)&wt[e][w][ko+4];
  }
  size_t base = (size_t)(nb+w)*KP + kb + ko;
  for(int b=0;b<BB;b++){
    float g[EE];
    *(float4*)&g[0] = *(float4*)&gsh[b*EE];
    *(float4*)&g[4] = *(float4*)&gsh[b*EE+4];
    float acc[8];
#pragma unroll
    for(int j=0;j<8;j++){
      float a = 0.f;
#pragma unroll
      for(int e=0;e<EE;e++) a = fmaf(g[e], wr[e][j], a);
      acc[j]=a;
    }
    if(act){
      __half2 hh[4], ll[4];
#pragma unroll
      for(int j=0;j<4;j++){
        __half h0=__float2half_rn(acc[2*j]), h1=__float2half_rn(acc[2*j+1]);
        hh[j]=__halves2half2(h0,h1);
        ll[j]=__halves2half2(__float2half_rn(acc[2*j]  -__half2float(h0)),
                             __float2half_rn(acc[2*j+1]-__half2float(h1)));
      }
      size_t a0 = (size_t)b*DD*KP + base;
      *(uint4*)(g_wh+a0) = *(uint4*)hh;
      *(uint4*)(g_wl+a0) = *(uint4*)ll;
    }
  }
}

// ------------- kernel 2: per-batch split-fp16 GEMM, n-sliced warps -----------
// grid (4 n-tiles, 128 batches), 256 threads. Warp w owns cols [16w,16w+16),
// loops 7 m16 tiles (M=112 >= 100). B frags loaded once per k16, reused 7x.
// smem: Ah 0 | Al 16K | Bh0 32K | Bl0 48K | Bh1 64K | Bl1 80K | bias 96K
extern __shared__ char smdyn[];
__global__ __launch_bounds__(256,2) void k_gemm(const float* __restrict__ x,
        const float* __restrict__ bias,
        const float* __restrict__ c0, const float* __restrict__ c1,
        float* __restrict__ out){
  int nt = blockIdx.x, b = blockIdx.y;
  float* sBias = (float*)(smdyn+98304);
  __shared__ float gg[EE];
  int tid = threadIdx.x, w = tid>>5, l = tid&31;
  if(tid==0){
    bool m0 = c0_is_mask(c0);
    const float* logits = m0 ? c1 : c0;
    const int*   masks  = m0 ? (const int*)c0 : (const int*)c1;
    float g[EE];
    gates_row(logits, masks, b, g);
#pragma unroll
    for(int e=0;e<EE;e++) gg[e]=g[e];
  }
  __syncthreads();
  if(tid<128){
    float s=0.f;
#pragma unroll
    for(int e=0;e<EE;e++) s += gg[e]*bias[e*DD + nt*128 + tid];
    sBias[tid]=s;
  }
  float cc[7][2][4];
#pragma unroll
  for(int mt=0;mt<7;mt++)
#pragma unroll
    for(int p=0;p<2;p++){ cc[mt][p][0]=0;cc[mt][p][1]=0;cc[mt][p][2]=0;cc[mt][p][3]=0; }
  const float*  xb = x + (size_t)b*LL*K0;
  const __half* bh = g_wh + ((size_t)b*DD + nt*128)*KP;
  const __half* bl = g_wl + ((size_t)b*DD + nt*128)*KP;
  uint32_t uAh=su32(smdyn), uAl=su32(smdyn+16384);
  uint32_t uB[2][2] = {{su32(smdyn+32768), su32(smdyn+49152)},
                       {su32(smdyn+65536), su32(smdyn+81920)}};

  // B cp.async mapping: 2 threads per n-row, 3x16B segs each (48 halves/row)
  int bn_row = tid>>1, bn_s0 = (tid&1)*3;
  // prologue: async B chunk 0 -> buffer 0
  {
#pragma unroll
    for(int s=0;s<3;s++){
      int ko = (bn_s0+s)*8;
      size_t go = (size_t)bn_row*KP + ko;
      int o = boff(bn_row, ko);
      cpa16(uB[0][0]+o, bh+go);
      cpa16(uB[0][1]+o, bl+go);
    }
    CP_COMMIT();
  }

  for(int ci=0; ci<NCH; ci++){
    int kb = ci*KC, cur = ci&1;
    __syncthreads();                     // previous MMA done (smem reusable)
    // A tile: 112 rows x 48 k (zero-pad rows>=100, k>=900): 1344 float4 slots
#pragma unroll
    for(int t=0;t<6;t++){
      int q = tid + t*256;
      if(q < 1344){
        int r = q/12, c = (q%12)<<2;
        float4 v = make_float4(0.f,0.f,0.f,0.f);
        if(r<LL && kb+c<K0) v = *(const float4*)(xb + (size_t)r*K0 + kb + c);
        __half h0=__float2half_rn(v.x), h1=__float2half_rn(v.y);
        __half h2=__float2half_rn(v.z), h3=__float2half_rn(v.w);
        __half q0=__float2half_rn(v.x-__half2float(h0)), q1=__float2half_rn(v.y-__half2float(h1));
        __half q2=__float2half_rn(v.z-__half2float(h2)), q3=__float2half_rn(v.w-__half2float(h3));
        int o = boff(r,c);
        *(__half2*)(smdyn+o)         = __halves2half2(h0,h1);
        *(__half2*)(smdyn+o+4)       = __halves2half2(h2,h3);
        *(__half2*)(smdyn+16384+o)   = __halves2half2(q0,q1);
        *(__half2*)(smdyn+16384+o+4) = __halves2half2(q2,q3);
      }
    }
    // async B for chunk ci+1 into other buffer; drain chunk ci's group
    if(ci < NCH-1){
      int kb2 = kb + KC;
#pragma unroll
      for(int s=0;s<3;s++){
        int ko = (bn_s0+s)*8;
        size_t go = (size_t)bn_row*KP + kb2 + ko;
        int o = boff(bn_row, ko);
        cpa16(uB[cur^1][0]+o, bh+go);
        cpa16(uB[cur^1][1]+o, bl+go);
      }
      CP_COMMIT();
      CP_WAIT1();
    } else {
      CP_WAIT0();
    }
    __syncthreads();
    uint32_t uBh = uB[cur][0], uBl = uB[cur][1];
#pragma unroll
    for(int ks3=0;ks3<3;ks3++){
      int ks = ks3<<4;
      // warp's B frags: n16 slice [16w,16w+16), both k halves
      int bn = (w<<4) + (l&7) + ((l&16)?8:0);
      int bo = boff(bn, ks + (l&8));
      uint32_t Bh[4], Bl[4];
      LDM4(Bh[0],Bh[1],Bh[2],Bh[3], uBh+bo);
      LDM4(Bl[0],Bl[1],Bl[2],Bl[3], uBl+bo);
#pragma unroll
      for(int mt=0;mt<7;mt++){
        int ar = (mt<<4) + (l&15);
        int ao = boff(ar, ks + ((l>>4)<<3));
        uint32_t Ah[4], Al[4];
        LDM4(Ah[0],Ah[1],Ah[2],Ah[3], uAh+ao);
        LDM4(Al[0],Al[1],Al[2],Al[3], uAl+ao);
        MMA(cc[mt][0], Ah,Bh[0],Bh[1]); MMA(cc[mt][0], Al,Bh[0],Bh[1]); MMA(cc[mt][0], Ah,Bl[0],Bl[1]);
        MMA(cc[mt][1], Ah,Bh[2],Bh[3]); MMA(cc[mt][1], Al,Bh[2],Bh[3]); MMA(cc[mt][1], Ah,Bl[2],Bl[3]);
      }
    }
  }
  // epilogue: +bias, bf16-round, store as f32, rows<100 only
#pragma unroll
  for(int mt=0;mt<7;mt++){
    int r0 = (mt<<4) + (l>>2);
#pragma unroll
    for(int p=0;p<2;p++){
      int nl = (w<<4) + (p<<3) + ((l&3)<<1);
      int n  = nt*128 + nl;
      float b0 = sBias[nl], b1 = sBias[nl+1];
      if(r0 < LL){
        float2 vv = make_float2(bf16r(cc[mt][p][0]+b0), bf16r(cc[mt][p][1]+b1));
        *(float2*)(out + (size_t)(b*LL + r0)*DD + n) = vv;
      }
      if(r0+8 < LL){
        float2 vv = make_float2(bf16r(cc[mt][p][2]+b0), bf16r(cc[mt][p][3]+b1));
        *(float2*)(out + (size_t)(b*LL + r0+8)*DD + n) = vv;
      }
    }
  }
}

extern "C" void kernel_launch(void* const* d_in, const int* in_sizes, int n_in,
                              void* d_out, int out_size){
  // Identify inputs by element count (robust to metadata ordering):
  // x: 11,520,000   W: 3,686,400   b: 4096   logits/masks: 1024 each
  const float* x = nullptr; const float* W = nullptr; const float* bias = nullptr;
  const float* c0 = nullptr; const float* c1 = nullptr;
  for(int i=0;i<n_in;i++){
    int s = in_sizes[i];
    if(s == BB*LL*3*300)      x    = (const float*)d_in[i];
    else if(s == EE*K0*DD)    W    = (const float*)d_in[i];
    else if(s == EE*DD)       bias = (const float*)d_in[i];
    else if(s == BB*EE){ if(!c0) c0 = (const float*)d_in[i]; else c1 = (const float*)d_in[i]; }
  }
  float* out = (float*)d_out;
  int tail = out_size - OUTM; if(tail < 0) tail = 0;
  cudaFuncSetAttribute(k_gemm, cudaFuncAttributeMaxDynamicSharedMemorySize, 98816);
  k_mix<<<dim3(4,64), 256>>>(W, c0, c1, out, tail);
  k_gemm<<<dim3(4,BB), 256, 98816>>>(x, bias, c0, c1, out);
}

// round 15
// speedup vs baseline: 1.0928x; 1.0928x over previous
#include <cuda_runtime.h>
#include <cuda_fp16.h>
#include <cuda_bf16.h>
#include <cstdint>

#define BB 128
#define LL 100
#define DD 512
#define EE 8
#define K0 900
#define KP 960
#define KC 64
#define NCH 15
#define OUTM (BB*LL*DD)

// scratch (device globals; no allocation allowed)
__device__ __half g_wh[(size_t)BB*DD*KP];   // mixed weights hi, [b][n][k], 126MB
__device__ __half g_wl[(size_t)BB*DD*KP];   // mixed weights lo

__device__ __forceinline__ uint32_t su32(const void* p){
  uint32_t a;
  asm("{ .reg .u64 t; cvta.to.shared.u64 t, %1; cvt.u32.u64 %0, t; }":"=r"(a):"l"(p));
  return a;
}
// swizzled byte offset inside a [rows][64 halves] tile (128B rows, SW over 16B groups)
__device__ __forceinline__ int boff(int r,int c){
  return r*128 + ((((c>>3)^(r&7))<<4) | ((c&7)<<1));
}
#define LDM4(r0,r1,r2,r3,a) \
  asm volatile("ldmatrix.sync.aligned.m8n8.x4.shared.b16 {%0,%1,%2,%3},[%4];" \
    :"=r"(r0),"=r"(r1),"=r"(r2),"=r"(r3):"r"(a))
#define MMA(c,a,b0,b1) \
  asm volatile("mma.sync.aligned.m16n8k16.row.col.f32.f16.f16.f32 " \
    "{%0,%1,%2,%3},{%4,%5,%6,%7},{%8,%9},{%0,%1,%2,%3};" \
    :"+f"((c)[0]),"+f"((c)[1]),"+f"((c)[2]),"+f"((c)[3]) \
    :"r"((a)[0]),"r"((a)[1]),"r"((a)[2]),"r"((a)[3]),"r"(b0),"r"(b1))

__device__ __forceinline__ void cpa16(uint32_t dst, const __half* src){
  unsigned long long g = __cvta_generic_to_global((const void*)src);
  asm volatile("cp.async.cg.shared.global [%0], [%1], 16;" :: "r"(dst), "l"(g));
}
#define CP_COMMIT() asm volatile("cp.async.commit_group;":::"memory")
#define CP_WAIT1()  asm volatile("cp.async.wait_group 1;":::"memory")
#define CP_WAIT0()  asm volatile("cp.async.wait_group 0;":::"memory")

__device__ __forceinline__ float bf16r(float x){
  return __bfloat162float(__float2bfloat16_rn(x));
}

// returns true if c0 is the int mask (row 0 bit-patterns all <= 1)
__device__ __forceinline__ bool c0_is_mask(const float* c0){
  const unsigned* u0 = (const unsigned*)c0;
  bool m = true;
#pragma unroll
  for(int e=0;e<EE;e++) if(u0[e] > 1u) m = false;
  return m;
}
// renormalized gates for batch row b into g[8]; returns pre-renorm masked sum
__device__ __forceinline__ float gates_row(const float* logits, const int* masks,
                                           int b, float* g){
  float v[EE]; float mx = -1e30f;
#pragma unroll
  for(int e=0;e<EE;e++){ v[e]=logits[b*EE+e]; mx=fmaxf(mx,v[e]); }
  float s=0.f;
#pragma unroll
  for(int e=0;e<EE;e++){ v[e]=expf(v[e]-mx); s+=v[e]; }
  float inv=1.f/s, gs=0.f;
#pragma unroll
  for(int e=0;e<EE;e++){ float r=v[e]*inv*((masks[b*EE+e]==1)?1.f:0.f); v[e]=r; gs+=r; }
  float rn=1.f/(gs+1e-9f);
#pragma unroll
  for(int e=0;e<EE;e++) g[e]=v[e]*rn;
  return gs;
}

// ------------- kernel 1: Wmix[b][n][k] = sum_e g[b,e] W[e,k,n], fp16 hi/lo ---
// grid (4 k-chunks of 256, 64 n-chunks of 8), 256 threads. Gates inline;
// block (0,0) writes the guide-loss tail.
__global__ __launch_bounds__(256) void k_mix(const float* __restrict__ W,
        const float* __restrict__ c0, const float* __restrict__ c1,
        float* __restrict__ out, int tail){
  __shared__ float wt[EE][8][264];
  __shared__ float gsh[BB*EE];
  __shared__ float red[BB];
  int tid = threadIdx.x;
  int kb = blockIdx.x*256, nb = blockIdx.y*8;
  bool m0 = c0_is_mask(c0);
  const float* logits = m0 ? c1 : c0;
  const int*   masks  = m0 ? (const int*)c0 : (const int*)c1;
  if(tid < BB){
    float g[EE];
    red[tid] = gates_row(logits, masks, tid, g);
#pragma unroll
    for(int e=0;e<EE;e++) gsh[tid*EE+e] = g[e];
  }
  for(int i=tid;i<EE*256*8;i+=256){
    int e=i>>11, k2=(i>>3)&255, n2=i&7;
    int k=kb+k2;
    wt[e][n2][k2] = (k<K0) ? W[((size_t)e*K0+k)*DD + nb+n2] : 0.f;
  }
  __syncthreads();
  if(blockIdx.x==0 && blockIdx.y==0 && tid==0){
    float t=0.f;
    for(int i=0;i<BB;i++) t+=red[i];
    float loss = 1.f - t/128.f; loss*=loss;
    for(int i=0;i<tail;i++) out[OUTM+i]=loss;
  }
  int w = tid>>5, l = tid&31;
  int ko = l*8;
  bool act = (kb + ko) < KP;         // kb=768 chunk: lanes 0..23 only
  float wr[EE][8];
#pragma unroll
  for(int e=0;e<EE;e++){
    *(float4*)&wr[e][0] = *(float4*)&wt[e][w][ko];
    *(float4*)&wr[e][4] = *(float4*)&wt[e][w][ko+4];
  }
  size_t base = (size_t)(nb+w)*KP + kb + ko;
  for(int b=0;b<BB;b++){
    float g[EE];
    *(float4*)&g[0] = *(float4*)&gsh[b*EE];
    *(float4*)&g[4] = *(float4*)&gsh[b*EE+4];
    float acc[8];
#pragma unroll
    for(int j=0;j<8;j++){
      float a = 0.f;
#pragma unroll
      for(int e=0;e<EE;e++) a = fmaf(g[e], wr[e][j], a);
      acc[j]=a;
    }
    if(act){
      __half2 hh[4], ll[4];
#pragma unroll
      for(int j=0;j<4;j++){
        __half h0=__float2half_rn(acc[2*j]), h1=__float2half_rn(acc[2*j+1]);
        hh[j]=__halves2half2(h0,h1);
        ll[j]=__halves2half2(__float2half_rn(acc[2*j]  -__half2float(h0)),
                             __float2half_rn(acc[2*j+1]-__half2float(h1)));
      }
      size_t a0 = (size_t)b*DD*KP + base;
      *(uint4*)(g_wh+a0) = *(uint4*)hh;
      *(uint4*)(g_wl+a0) = *(uint4*)ll;
    }
  }
}

// ------------- kernel 2: per-batch split-fp16 GEMM (R10 layout, MMA reorder) -
// grid (4 n-tiles, 128 batches), 256 threads (8 warps, warp w -> rows 16w..16w+15)
// smem: Ah 0 | Al 16K | Bh0 32K | Bl0 48K | Bh1 64K | Bl1 80K | bias 96K
extern __shared__ char smdyn[];
__global__ __launch_bounds__(256,2) void k_gemm(const float* __restrict__ x,
        const float* __restrict__ bias,
        const float* __restrict__ c0, const float* __restrict__ c1,
        float* __restrict__ out){
  int nt = blockIdx.x, b = blockIdx.y;
  float* sBias = (float*)(smdyn+98304);
  __shared__ float gg[EE];
  int tid = threadIdx.x, w = tid>>5, l = tid&31;
  if(tid==0){
    bool m0 = c0_is_mask(c0);
    const float* logits = m0 ? c1 : c0;
    const int*   masks  = m0 ? (const int*)c0 : (const int*)c1;
    float g[EE];
    gates_row(logits, masks, b, g);
#pragma unroll
    for(int e=0;e<EE;e++) gg[e]=g[e];
  }
  __syncthreads();
  if(tid<128){
    float s=0.f;
#pragma unroll
    for(int e=0;e<EE;e++) s += gg[e]*bias[e*DD + nt*128 + tid];
    sBias[tid]=s;
  }
  float cc[16][4];
#pragma unroll
  for(int j=0;j<16;j++){ cc[j][0]=0;cc[j][1]=0;cc[j][2]=0;cc[j][3]=0; }
  const float*  xb = x + (size_t)b*LL*K0;
  const __half* bh = g_wh + ((size_t)b*DD + nt*128)*KP;
  const __half* bl = g_wl + ((size_t)b*DD + nt*128)*KP;
  uint32_t uAh=su32(smdyn), uAl=su32(smdyn+16384);
  uint32_t uB[2][2] = {{su32(smdyn+32768), su32(smdyn+49152)},
                       {su32(smdyn+65536), su32(smdyn+81920)}};

  // prologue: async B chunk 0 -> buffer 0
  {
#pragma unroll
    for(int t=0;t<4;t++){
      int q = tid + t*256;
      int n = q>>3, c = (q&7)<<3;
      size_t go = (size_t)n*KP + c;
      int o = boff(n,c);
      cpa16(uB[0][0]+o, bh+go);
      cpa16(uB[0][1]+o, bl+go);
    }
    CP_COMMIT();
  }

  for(int ci=0; ci<NCH; ci++){
    int kb = ci*KC, cur = ci&1;
    __syncthreads();                     // previous MMA done (A smem reusable)
    // A tile (fp32 x -> hi/lo fp16), rows>=100 and k>=900 zero-padded
#pragma unroll
    for(int t=0;t<8;t++){
      int q = tid + t*256;
      int r = q>>4, c = (q&15)<<2;
      float4 v = make_float4(0.f,0.f,0.f,0.f);
      if(r<LL && kb+c<K0) v = *(const float4*)(xb + r*K0 + kb + c);
      __half h0=__float2half_rn(v.x), h1=__float2half_rn(v.y);
      __half h2=__float2half_rn(v.z), h3=__float2half_rn(v.w);
      __half q0=__float2half_rn(v.x-__half2float(h0)), q1=__float2half_rn(v.y-__half2float(h1));
      __half q2=__float2half_rn(v.z-__half2float(h2)), q3=__float2half_rn(v.w-__half2float(h3));
      int o = boff(r,c);
      *(__half2*)(smdyn+o)         = __halves2half2(h0,h1);
      *(__half2*)(smdyn+o+4)       = __halves2half2(h2,h3);
      *(__half2*)(smdyn+16384+o)   = __halves2half2(q0,q1);
      *(__half2*)(smdyn+16384+o+4) = __halves2half2(q2,q3);
    }
    // async B for chunk ci+1 into the other buffer, then drain chunk ci's group
    if(ci < NCH-1){
      int kb2 = kb + KC;
#pragma unroll
      for(int t=0;t<4;t++){
        int q = tid + t*256;
        int n = q>>3, c = (q&7)<<3;
        size_t go = (size_t)n*KP + kb2 + c;
        int o = boff(n,c);
        cpa16(uB[cur^1][0]+o, bh+go);
        cpa16(uB[cur^1][1]+o, bl+go);
      }
      CP_COMMIT();
      CP_WAIT1();                        // chunk ci's B resident
    } else {
      CP_WAIT0();
    }
    __syncthreads();
    uint32_t uBh = uB[cur][0], uBl = uB[cur][1];
#pragma unroll
    for(int ks4=0;ks4<4;ks4++){
      int ks = ks4<<4;
      uint32_t Ah[4], Al[4];
      int ar = (w<<4) + (l&15);
      int ao = boff(ar, ks + ((l>>4)<<3));
      LDM4(Ah[0],Ah[1],Ah[2],Ah[3], uAh+ao);
      LDM4(Al[0],Al[1],Al[2],Al[3], uAl+ao);
#pragma unroll
      for(int j=0;j<8;j++){
        int bn = (j<<4) + (l&7) + ((l&16)?8:0);
        int bo = boff(bn, ks + (l&8));
        uint32_t Bh[4], Bl[4];
        LDM4(Bh[0],Bh[1],Bh[2],Bh[3], uBh+bo);
        LDM4(Bl[0],Bl[1],Bl[2],Bl[3], uBl+bo);
        // reordered: alternate accumulators -> RAW distance 2, per-acc
        // product order (hh, lh, hl) unchanged => bit-identical result
        MMA(cc[2*j],  Ah,Bh[0],Bh[1]);
        MMA(cc[2*j+1],Ah,Bh[2],Bh[3]);
        MMA(cc[2*j],  Al,Bh[0],Bh[1]);
        MMA(cc[2*j+1],Al,Bh[2],Bh[3]);
        MMA(cc[2*j],  Ah,Bl[0],Bl[1]);
        MMA(cc[2*j+1],Ah,Bl[2],Bl[3]);
      }
    }
  }
  // epilogue: +bias, bf16-round, store as f32, rows<100 only
  int r0 = (w<<4) + (l>>2);
#pragma unroll
  for(int j=0;j<16;j++){
    int nl = (j<<3) + ((l&3)<<1);
    int n  = nt*128 + nl;
    float b0 = sBias[nl], b1 = sBias[nl+1];
    if(r0 < LL){
      float2 vv = make_float2(bf16r(cc[j][0]+b0), bf16r(cc[j][1]+b1));
      *(float2*)(out + (size_t)(b*LL + r0)*DD + n) = vv;
    }
    if(r0+8 < LL){
      float2 vv = make_float2(bf16r(cc[j][2]+b0), bf16r(cc[j][3]+b1));
      *(float2*)(out + (size_t)(b*LL + r0+8)*DD + n) = vv;
    }
  }
}

extern "C" void kernel_launch(void* const* d_in, const int* in_sizes, int n_in,
                              void* d_out, int out_size){
  // Identify inputs by element count (robust to metadata ordering):
  // x: 11,520,000   W: 3,686,400   b: 4096   logits/masks: 1024 each
  const float* x = nullptr; const float* W = nullptr; const float* bias = nullptr;
  const float* c0 = nullptr; const float* c1 = nullptr;
  for(int i=0;i<n_in;i++){
    int s = in_sizes[i];
    if(s == BB*LL*3*300)      x    = (const float*)d_in[i];
    else if(s == EE*K0*DD)    W    = (const float*)d_in[i];
    else if(s == EE*DD)       bias = (const float*)d_in[i];
    else if(s == BB*EE){ if(!c0) c0 = (const float*)d_in[i]; else c1 = (const float*)d_in[i]; }
  }
  float* out = (float*)d_out;
  int tail = out_size - OUTM; if(tail < 0) tail = 0;
  cudaFuncSetAttribute(k_gemm, cudaFuncAttributeMaxDynamicSharedMemorySize, 98816);
  k_mix<<<dim3(4,64), 256>>>(W, c0, c1, out, tail);
  k_gemm<<<dim3(4,BB), 256, 98816>>>(x, bias, c0, c1, out);
}

// round 17
// speedup vs baseline: 1.0985x; 1.0053x over previous
#include <cuda_runtime.h>
#include <cuda_fp16.h>
#include <cuda_bf16.h>
#include <cstdint>

#define BB 128
#define LL 100
#define DD 512
#define EE 8
#define K0 900
#define KP 960
#define KC 64
#define NCH 15
#define OUTM (BB*LL*DD)

// scratch (device globals; no allocation allowed)
__device__ __half g_wh[(size_t)BB*DD*KP];   // mixed weights hi, [b][n][k], 126MB
__device__ __half g_wl[(size_t)BB*DD*KP];   // mixed weights lo

__device__ __forceinline__ uint32_t su32(const void* p){
  uint32_t a;
  asm("{ .reg .u64 t; cvta.to.shared.u64 t, %1; cvt.u32.u64 %0, t; }":"=r"(a):"l"(p));
  return a;
}
// swizzled byte offset inside a [rows][64 halves] tile (128B rows, SW over 16B groups)
__device__ __forceinline__ int boff(int r,int c){
  return r*128 + ((((c>>3)^(r&7))<<4) | ((c&7)<<1));
}
#define LDM4(r0,r1,r2,r3,a) \
  asm volatile("ldmatrix.sync.aligned.m8n8.x4.shared.b16 {%0,%1,%2,%3},[%4];" \
    :"=r"(r0),"=r"(r1),"=r"(r2),"=r"(r3):"r"(a))
#define MMA(c,a,b0,b1) \
  asm volatile("mma.sync.aligned.m16n8k16.row.col.f32.f16.f16.f32 " \
    "{%0,%1,%2,%3},{%4,%5,%6,%7},{%8,%9},{%0,%1,%2,%3};" \
    :"+f"((c)[0]),"+f"((c)[1]),"+f"((c)[2]),"+f"((c)[3]) \
    :"r"((a)[0]),"r"((a)[1]),"r"((a)[2]),"r"((a)[3]),"r"(b0),"r"(b1))

__device__ __forceinline__ void cpa16(uint32_t dst, const __half* src){
  unsigned long long g = __cvta_generic_to_global((const void*)src);
  asm volatile("cp.async.cg.shared.global [%0], [%1], 16;" :: "r"(dst), "l"(g));
}
#define CP_COMMIT() asm volatile("cp.async.commit_group;":::"memory")
#define CP_WAIT1()  asm volatile("cp.async.wait_group 1;":::"memory")
#define CP_WAIT0()  asm volatile("cp.async.wait_group 0;":::"memory")

__device__ __forceinline__ float bf16r(float x){
  return __bfloat162float(__float2bfloat16_rn(x));
}

// returns true if c0 is the int mask (row 0 bit-patterns all <= 1)
__device__ __forceinline__ bool c0_is_mask(const float* c0){
  const unsigned* u0 = (const unsigned*)c0;
  bool m = true;
#pragma unroll
  for(int e=0;e<EE;e++) if(u0[e] > 1u) m = false;
  return m;
}
// renormalized gates for batch row b into g[8]; returns pre-renorm masked sum
__device__ __forceinline__ float gates_row(const float* logits, const int* masks,
                                           int b, float* g){
  float v[EE]; float mx = -1e30f;
#pragma unroll
  for(int e=0;e<EE;e++){ v[e]=logits[b*EE+e]; mx=fmaxf(mx,v[e]); }
  float s=0.f;
#pragma unroll
  for(int e=0;e<EE;e++){ v[e]=expf(v[e]-mx); s+=v[e]; }
  float inv=1.f/s, gs=0.f;
#pragma unroll
  for(int e=0;e<EE;e++){ float r=v[e]*inv*((masks[b*EE+e]==1)?1.f:0.f); v[e]=r; gs+=r; }
  float rn=1.f/(gs+1e-9f);
#pragma unroll
  for(int e=0;e<EE;e++) g[e]=v[e]*rn;
  return gs;
}

// ------------- kernel 1: Wmix[b][n][k] = sum_e g[b,e] W[e,k,n], fp16 hi/lo ---
// grid (4 k-chunks of 256, 64 n-chunks of 8), 256 threads. Gates inline;
// block (0,0) writes the guide-loss tail.
__global__ __launch_bounds__(256) void k_mix(const float* __restrict__ W,
        const float* __restrict__ c0, const float* __restrict__ c1,
        float* __restrict__ out, int tail){
  __shared__ float wt[EE][8][264];
  __shared__ float gsh[BB*EE];
  __shared__ float red[BB];
  int tid = threadIdx.x;
  int kb = blockIdx.x*256, nb = blockIdx.y*8;
  bool m0 = c0_is_mask(c0);
  const float* logits = m0 ? c1 : c0;
  const int*   masks  = m0 ? (const int*)c0 : (const int*)c1;
  if(tid < BB){
    float g[EE];
    red[tid] = gates_row(logits, masks, tid, g);
#pragma unroll
    for(int e=0;e<EE;e++) gsh[tid*EE+e] = g[e];
  }
  for(int i=tid;i<EE*256*8;i+=256){
    int e=i>>11, k2=(i>>3)&255, n2=i&7;
    int k=kb+k2;
    wt[e][n2][k2] = (k<K0) ? W[((size_t)e*K0+k)*DD + nb+n2] : 0.f;
  }
  __syncthreads();
  if(blockIdx.x==0 && blockIdx.y==0 && tid==0){
    float t=0.f;
    for(int i=0;i<BB;i++) t+=red[i];
    float loss = 1.f - t/128.f; loss*=loss;
    for(int i=0;i<tail;i++) out[OUTM+i]=loss;
  }
  int w = tid>>5, l = tid&31;
  int ko = l*8;
  bool act = (kb + ko) < KP;         // kb=768 chunk: lanes 0..23 only
  float wr[EE][8];
#pragma unroll
  for(int e=0;e<EE;e++){
    *(float4*)&wr[e][0] = *(float4*)&wt[e][w][ko];
    *(float4*)&wr[e][4] = *(float4*)&wt[e][w][ko+4];
  }
  size_t base = (size_t)(nb+w)*KP + kb + ko;
  for(int b=0;b<BB;b++){
    float g[EE];
    *(float4*)&g[0] = *(float4*)&gsh[b*EE];
    *(float4*)&g[4] = *(float4*)&gsh[b*EE+4];
    float acc[8];
#pragma unroll
    for(int j=0;j<8;j++){
      float a = 0.f;
#pragma unroll
      for(int e=0;e<EE;e++) a = fmaf(g[e], wr[e][j], a);
      acc[j]=a;
    }
    if(act){
      __half2 hh[4], ll[4];
#pragma unroll
      for(int j=0;j<4;j++){
        __half h0=__float2half_rn(acc[2*j]), h1=__float2half_rn(acc[2*j+1]);
        hh[j]=__halves2half2(h0,h1);
        ll[j]=__halves2half2(__float2half_rn(acc[2*j]  -__half2float(h0)),
                             __float2half_rn(acc[2*j+1]-__half2float(h1)));
      }
      size_t a0 = (size_t)b*DD*KP + base;
      *(uint4*)(g_wh+a0) = *(uint4*)hh;
      *(uint4*)(g_wl+a0) = *(uint4*)ll;
    }
  }
}

// ------------- kernel 2: per-batch split-fp16 GEMM, 2D warp tiling 4m x 2n ---
// grid (4 n-tiles, 128 batches), 256 threads. Warp w: wm=w&3 (m32 slice),
// wn=w>>2 (n64 slice). Per k16: 4 A LDM4 + 8 B LDM4 (vs 18 m-sliced).
// smem: Ah 0 | Al 16K | Bh0 32K | Bl0 48K | Bh1 64K | Bl1 80K | bias 96K
extern __shared__ char smdyn[];
__global__ __launch_bounds__(256,2) void k_gemm(const float* __restrict__ x,
        const float* __restrict__ bias,
        const float* __restrict__ c0, const float* __restrict__ c1,
        float* __restrict__ out){
  int nt = blockIdx.x, b = blockIdx.y;
  float* sBias = (float*)(smdyn+98304);
  __shared__ float gg[EE];
  int tid = threadIdx.x, w = tid>>5, l = tid&31;
  int wm = w&3, wn = w>>2;
  if(tid==0){
    bool m0 = c0_is_mask(c0);
    const float* logits = m0 ? c1 : c0;
    const int*   masks  = m0 ? (const int*)c0 : (const int*)c1;
    float g[EE];
    gates_row(logits, masks, b, g);
#pragma unroll
    for(int e=0;e<EE;e++) gg[e]=g[e];
  }
  __syncthreads();
  if(tid<128){
    float s=0.f;
#pragma unroll
    for(int e=0;e<EE;e++) s += gg[e]*bias[e*DD + nt*128 + tid];
    sBias[tid]=s;
  }
  float cc[2][4][2][4];
#pragma unroll
  for(int mi=0;mi<2;mi++)
#pragma unroll
    for(int ni=0;ni<4;ni++)
#pragma unroll
      for(int p=0;p<2;p++){ cc[mi][ni][p][0]=0;cc[mi][ni][p][1]=0;cc[mi][ni][p][2]=0;cc[mi][ni][p][3]=0; }
  const float*  xb = x + (size_t)b*LL*K0;
  const __half* bh = g_wh + ((size_t)b*DD + nt*128)*KP;
  const __half* bl = g_wl + ((size_t)b*DD + nt*128)*KP;
  uint32_t uAh=su32(smdyn), uAl=su32(smdyn+16384);
  uint32_t uB[2][2] = {{su32(smdyn+32768), su32(smdyn+49152)},
                       {su32(smdyn+65536), su32(smdyn+81920)}};

  // prologue: async B chunk 0 -> buffer 0
  {
#pragma unroll
    for(int t=0;t<4;t++){
      int q = tid + t*256;
      int n = q>>3, c = (q&7)<<3;
      size_t go = (size_t)n*KP + c;
      int o = boff(n,c);
      cpa16(uB[0][0]+o, bh+go);
      cpa16(uB[0][1]+o, bl+go);
    }
    CP_COMMIT();
  }

  for(int ci=0; ci<NCH; ci++){
    int kb = ci*KC, cur = ci&1;
    __syncthreads();                     // previous MMA done (A smem reusable)
    // A tile (fp32 x -> hi/lo fp16), rows>=100 and k>=900 zero-padded
#pragma unroll
    for(int t=0;t<8;t++){
      int q = tid + t*256;
      int r = q>>4, c = (q&15)<<2;
      float4 v = make_float4(0.f,0.f,0.f,0.f);
      if(r<LL && kb+c<K0) v = *(const float4*)(xb + r*K0 + kb + c);
      __half h0=__float2half_rn(v.x), h1=__float2half_rn(v.y);
      __half h2=__float2half_rn(v.z), h3=__float2half_rn(v.w);
      __half q0=__float2half_rn(v.x-__half2float(h0)), q1=__float2half_rn(v.y-__half2float(h1));
      __half q2=__float2half_rn(v.z-__half2float(h2)), q3=__float2half_rn(v.w-__half2float(h3));
      int o = boff(r,c);
      *(__half2*)(smdyn+o)         = __halves2half2(h0,h1);
      *(__half2*)(smdyn+o+4)       = __halves2half2(h2,h3);
      *(__half2*)(smdyn+16384+o)   = __halves2half2(q0,q1);
      *(__half2*)(smdyn+16384+o+4) = __halves2half2(q2,q3);
    }
    // async B for chunk ci+1 into the other buffer, then drain chunk ci's group
    if(ci < NCH-1){
      int kb2 = kb + KC;
#pragma unroll
      for(int t=0;t<4;t++){
        int q = tid + t*256;
        int n = q>>3, c = (q&7)<<3;
        size_t go = (size_t)n*KP + kb2 + c;
        int o = boff(n,c);
        cpa16(uB[cur^1][0]+o, bh+go);
        cpa16(uB[cur^1][1]+o, bl+go);
      }
      CP_COMMIT();
      CP_WAIT1();                        // chunk ci's B resident
    } else {
      CP_WAIT0();
    }
    __syncthreads();
    uint32_t uBh = uB[cur][0], uBl = uB[cur][1];
#pragma unroll
    for(int ks4=0;ks4<4;ks4++){
      int ks = ks4<<4;
      uint32_t Ah[2][4], Al[2][4];
#pragma unroll
      for(int mi=0;mi<2;mi++){
        int ar = wm*32 + mi*16 + (l&15);
        int ao = boff(ar, ks + ((l>>4)<<3));
        LDM4(Ah[mi][0],Ah[mi][1],Ah[mi][2],Ah[mi][3], uAh+ao);
        LDM4(Al[mi][0],Al[mi][1],Al[mi][2],Al[mi][3], uAl+ao);
      }
#pragma unroll
      for(int ni=0;ni<4;ni++){
        int bn = wn*64 + ni*16 + (l&7) + ((l&16)?8:0);
        int bo = boff(bn, ks + (l&8));
        uint32_t Bh[4], Bl[4];
        LDM4(Bh[0],Bh[1],Bh[2],Bh[3], uBh+bo);
        LDM4(Bl[0],Bl[1],Bl[2],Bl[3], uBl+bo);
        // per-accumulator product order hh -> lh -> hl (bit-identical to R15);
        // RAW distance 4 via mi/p interleave
        MMA(cc[0][ni][0], Ah[0], Bh[0],Bh[1]);
        MMA(cc[1][ni][0], Ah[1], Bh[0],Bh[1]);
        MMA(cc[0][ni][1], Ah[0], Bh[2],Bh[3]);
        MMA(cc[1][ni][1], Ah[1], Bh[2],Bh[3]);
        MMA(cc[0][ni][0], Al[0], Bh[0],Bh[1]);
        MMA(cc[1][ni][0], Al[1], Bh[0],Bh[1]);
        MMA(cc[0][ni][1], Al[0], Bh[2],Bh[3]);
        MMA(cc[1][ni][1], Al[1], Bh[2],Bh[3]);
        MMA(cc[0][ni][0], Ah[0], Bl[0],Bl[1]);
        MMA(cc[1][ni][0], Ah[1], Bl[0],Bl[1]);
        MMA(cc[0][ni][1], Ah[0], Bl[2],Bl[3]);
        MMA(cc[1][ni][1], Ah[1], Bl[2],Bl[3]);
      }
    }
  }
  // epilogue: +bias, bf16-round, store as f32, rows<100 only
#pragma unroll
  for(int mi=0;mi<2;mi++){
    int r0 = wm*32 + mi*16 + (l>>2);
#pragma unroll
    for(int ni=0;ni<4;ni++)
#pragma unroll
      for(int p=0;p<2;p++){
        int nl = wn*64 + ni*16 + p*8 + ((l&3)<<1);
        int n  = nt*128 + nl;
        float b0 = sBias[nl], b1 = sBias[nl+1];
        if(r0 < LL){
          float2 vv = make_float2(bf16r(cc[mi][ni][p][0]+b0), bf16r(cc[mi][ni][p][1]+b1));
          *(float2*)(out + (size_t)(b*LL + r0)*DD + n) = vv;
        }
        if(r0+8 < LL){
          float2 vv = make_float2(bf16r(cc[mi][ni][p][2]+b0), bf16r(cc[mi][ni][p][3]+b1));
          *(float2*)(out + (size_t)(b*LL + r0+8)*DD + n) = vv;
        }
      }
  }
}

extern "C" void kernel_launch(void* const* d_in, const int* in_sizes, int n_in,
                              void* d_out, int out_size){
  // Identify inputs by element count (robust to metadata ordering):
  // x: 11,520,000   W: 3,686,400   b: 4096   logits/masks: 1024 each
  const float* x = nullptr; const float* W = nullptr; const float* bias = nullptr;
  const float* c0 = nullptr; const float* c1 = nullptr;
  for(int i=0;i<n_in;i++){
    int s = in_sizes[i];
    if(s == BB*LL*3*300)      x    = (const float*)d_in[i];
    else if(s == EE*K0*DD)    W    = (const float*)d_in[i];
    else if(s == EE*DD)       bias = (const float*)d_in[i];
    else if(s == BB*EE){ if(!c0) c0 = (const float*)d_in[i]; else c1 = (const float*)d_in[i]; }
  }
  float* out = (float*)d_out;
  int tail = out_size - OUTM; if(tail < 0) tail = 0;
  cudaFuncSetAttribute(k_gemm, cudaFuncAttributeMaxDynamicSharedMemorySize, 98816);
  k_mix<<<dim3(4,64), 256>>>(W, c0, c1, out, tail);
  k_gemm<<<dim3(4,BB), 256, 98816>>>(x, bias, c0, c1, out);
}